// round 6
// baseline (speedup 1.0000x reference)
#include <cuda_runtime.h>
#include <math.h>

#define T_ 64
#define M_ 256
#define K_ 6
#define B_ 256
#define H_ 256
#define L_ 128
#define V_ 780
#define E_ 16384
#define DC_ 383          // wcls cols = H+L-1
#define DS_ 638          // ucls cols = 2H+L-2
#define NROWS (E_ + B_)  // msg rows + root rows
#define NB_ 64           // scan blocks (must all be resident)

// ------------------------- device scratch --------------------------------
__device__ __align__(16) float  g_hbuf [(E_ + 1) * H_];
__device__ __align__(16) float  g_h1buf[(E_ + 1) * H_];
__device__ __align__(16) float  g_W1T  [512 * H_];      // full W1^T (for embW1 prep)
__device__ __align__(16) float  g_W1B  [H_ * H_];       // scan weights: row0=W1[:,0], rowk=W1[:,255+k]
__device__ __align__(16) float  g_W0T  [H_ * H_];
__device__ __align__(16) float  g_embW1[V_ * H_];       // emb_spatial @ W1^T_spatial
__device__ __align__(16) float  g_Gt   [384 * V_];
__device__ __align__(16) float  g_X    [NROWS * 384];
__device__ double g_acc[6];
__device__ volatile int g_bar[T_];

// ------------------------- helpers ---------------------------------------
__device__ __forceinline__ float blockReduceSum(float v, float* sh) {
    __syncthreads();
    #pragma unroll
    for (int o = 16; o > 0; o >>= 1) v += __shfl_down_sync(0xffffffffu, v, o);
    int tid = threadIdx.x;
    if ((tid & 31) == 0) sh[tid >> 5] = v;
    __syncthreads();
    if (tid < 32) {
        int nw = (blockDim.x + 31) >> 5;
        v = (tid < nw) ? sh[tid] : 0.f;
        #pragma unroll
        for (int o = 16; o > 0; o >>= 1) v += __shfl_down_sync(0xffffffffu, v, o);
        if (tid == 0) sh[0] = v;
    }
    __syncthreads();
    return sh[0];
}

// ------------------------- prep -------------------------------------------
__global__ void prep_misc(const float* __restrict__ W0,
                          const float* __restrict__ W1,
                          const float* __restrict__ wcls) {
    if (blockIdx.x == 0 && threadIdx.x < T_) g_bar[threadIdx.x] = 0;
    const int n1 = 512 * H_;        // W1T
    const int n2 = H_ * H_;         // W0T
    const int n3 = 384 * V_;        // Gt
    const int n4 = H_ * H_;         // W1B
    for (int idx = blockIdx.x * blockDim.x + threadIdx.x;
         idx < n1 + n2 + n3 + n4; idx += gridDim.x * blockDim.x) {
        if (idx < n1) {
            int i = idx >> 8, j = idx & 255;
            g_W1T[idx] = (i < 511) ? W1[j * 511 + i] : 0.f;
        } else if (idx < n1 + n2) {
            int k = idx - n1;
            int i = k >> 8, j = k & 255;
            g_W0T[k] = W0[j * H_ + i];
        } else if (idx < n1 + n2 + n3) {
            int k = idx - n1 - n2;
            int i = k / V_, v = k % V_;
            float g;
            if (i == 0)       g = -wcls[v * DC_];
            else if (i < DC_) g = wcls[v * DC_ + i];
            else              g = 0.f;
            g_Gt[k] = g;
        } else {
            int k = idx - n1 - n2 - n3;
            int i = k >> 8, j = k & 255;    // W1B[i][j]
            g_W1B[k] = (i == 0) ? W1[j * 511] : W1[j * 511 + 255 + i];
        }
    }
}

__global__ void prep_pad(const float* __restrict__ W0,
                         const float* __restrict__ b0,
                         const float* __restrict__ s0p) {
    __shared__ float red[32];
    __shared__ float ybc;
    int tid = threadIdx.x;
    if (tid < 6) g_acc[tid] = 0.0;
    g_hbuf[E_ * H_ + tid] = (tid == 0) ? 1.f : 0.f;
    float y = W0[tid * H_] + b0[tid];
    if (tid == 0) ybc = y;
    float ss = blockReduceSum((tid == 0) ? 0.f : y * y, red);
    float time = expf(s0p[0]) / (1.f + expf(-ybc)) + 1.1f;
    float sc = sqrtf((time * time - 1.f) / fmaxf(ss, 1e-8f));
    g_h1buf[E_ * H_ + tid] = (tid == 0) ? time : y * sc;
}

// embW1[v][j] = sum_{i=1..255} emb[v][i] * W1T[i][j]   (16 v-rows per block)
__global__ void prep_embW1(const float* __restrict__ emb) {
    __shared__ float es[16][256];
    int v0 = blockIdx.x * 16, tid = threadIdx.x;
    for (int i = tid; i < 16 * 256; i += 256) {
        int r = i >> 8, c = i & 255;
        es[r][c] = (v0 + r < V_) ? emb[(v0 + r) * H_ + c] : 0.f;
    }
    __syncthreads();
    float acc[16];
    #pragma unroll
    for (int r = 0; r < 16; r++) acc[r] = 0.f;
    for (int i = 1; i < 256; i++) {
        float w = g_W1T[i * H_ + tid];
        #pragma unroll
        for (int r = 0; r < 16; r++) acc[r] += es[r][i] * w;
    }
    #pragma unroll
    for (int r = 0; r < 16; r++)
        if (v0 + r < V_) g_embW1[(v0 + r) * H_ + tid] = acc[r];
}

// ------------------------- persistent scan kernel -------------------------
// 64 blocks x 512 threads. col = tid&255, half = tid>>8.
// Each half owns 2 rows (r = half*2 + rr), full K. Weights staged through
// double-buffered smem in 32-row chunks.
__global__ void __launch_bounds__(512, 1) scan_kernel(
    const int*   __restrict__ wid,
    const int*   __restrict__ nhi,
    const float* __restrict__ nhw,
    const float* __restrict__ emb,
    const float* __restrict__ b0,
    const float* __restrict__ s0p,
    const float* __restrict__ b1,
    const float* __restrict__ s1p) {
    extern __shared__ float dyn[];
    float* sW   = dyn;                 // 2 x 32 x 256 = 16384 floats
    float* svec = dyn + 16384;         // 4 x 256
    float* shv  = dyn + 16384 + 1024;  // 4 x 256
    __shared__ float redsh[4][8];
    __shared__ float ybc[4];

    int tid  = threadIdx.x;
    int col  = tid & 255;
    int half = tid >> 8;
    int warp = tid >> 5;
    int lane = tid & 31;
    int bx   = blockIdx.x;
    float e_s0 = expf(s0p[0]);
    float e_s1 = expf(s1p[0]);
    float bias1 = b1[col];
    float bias0 = b0[col];

    const float4* w1b4 = (const float4*)g_W1B;
    const float4* w0t4 = (const float4*)g_W0T;
    float4* sW4 = (float4*)sW;

    for (int t = 0; t < T_; t++) {
        int ebase = t * M_ + bx * 4;

        // ---- phase 1: gathered midpoint on h1buf, build svec -------------
        #pragma unroll
        for (int rr = 0; rr < 2; rr++) {
            int r = half * 2 + rr;
            int e = ebase + r;
            float wsum = 0.f, a = 0.f;
            #pragma unroll
            for (int k = 0; k < K_; k++) {
                int   id = nhi[e * K_ + k];
                float w  = nhw[e * K_ + k];
                wsum += w;
                a += w * g_h1buf[id * H_ + col];
            }
            a /= fmaxf(wsum, 1e-8f);
            float v = (col == 0) ? a * a : -a * a;
            #pragma unroll
            for (int o = 16; o > 0; o >>= 1) v += __shfl_down_sync(0xffffffffu, v, o);
            if (lane == 0) redsh[r][warp & 7] = v;
            __syncthreads();
            float inn = 0.f;
            #pragma unroll
            for (int w8 = 0; w8 < 8; w8++) inn += redsh[r][w8];
            float h1m = a / sqrtf(fmaxf(inn, 1e-8f));
            if (col == 0) {
                float cx0 = emb[wid[e] * H_];
                svec[r * 256] = sqrtf(fmaxf(cx0 * cx0 + h1m * h1m - 1.0f, 1e-8f));
            } else {
                svec[r * 256 + col] = h1m;
            }
            __syncthreads();
        }

        // ---- phase 2: Y = svec @ W1B (K=256, staged smem, 8 chunks) ------
        float a0 = 0.f, a1 = 0.f;
        {
            // stage chunk 0
            for (int f = tid; f < 2048; f += 512) sW4[f] = w1b4[f];
            __syncthreads();
            #pragma unroll 1
            for (int c = 0; c < 8; c++) {
                if (c < 7) {
                    const float4* src = w1b4 + (c + 1) * 2048;
                    float4* dst = sW4 + ((c + 1) & 1) * 2048;
                    for (int f = tid; f < 2048; f += 512) dst[f] = src[f];
                }
                const float* wb = sW + (c & 1) * 8192;
                const float4* x0v = (const float4*)(svec + (half * 2 + 0) * 256 + c * 32);
                const float4* x1v = (const float4*)(svec + (half * 2 + 1) * 256 + c * 32);
                #pragma unroll
                for (int k4 = 0; k4 < 8; k4++) {
                    float w0 = wb[(k4 * 4 + 0) * 256 + col];
                    float w1 = wb[(k4 * 4 + 1) * 256 + col];
                    float w2 = wb[(k4 * 4 + 2) * 256 + col];
                    float w3 = wb[(k4 * 4 + 3) * 256 + col];
                    float4 xa = x0v[k4], xb = x1v[k4];
                    a0 += w0 * xa.x + w1 * xa.y + w2 * xa.z + w3 * xa.w;
                    a1 += w0 * xb.x + w1 * xb.y + w2 * xb.z + w3 * xb.w;
                }
                __syncthreads();
            }
        }
        // epilogue: add embW1 + bias, llinear, write hbuf + shv
        {
            float y[2];
            float accv[2] = {a0, a1};
            #pragma unroll
            for (int rr = 0; rr < 2; rr++) {
                int r = half * 2 + rr;
                int e = ebase + r;
                y[rr] = accv[rr] + g_embW1[wid[e] * H_ + col] + bias1;
                float v = (col == 0) ? 0.f : y[rr] * y[rr];
                #pragma unroll
                for (int o = 16; o > 0; o >>= 1) v += __shfl_down_sync(0xffffffffu, v, o);
                if (lane == 0) redsh[r][warp & 7] = v;
                if (col == 0) ybc[r] = y[rr];
            }
            __syncthreads();
            #pragma unroll
            for (int rr = 0; rr < 2; rr++) {
                int r = half * 2 + rr;
                float ss = 0.f;
                #pragma unroll
                for (int w8 = 0; w8 < 8; w8++) ss += redsh[r][w8];
                float time = e_s1 / (1.f + expf(-ybc[r])) + 1.1f;
                float sc = sqrtf((time * time - 1.f) / fmaxf(ss, 1e-8f));
                float outv = (col == 0) ? time : y[rr] * sc;
                g_hbuf[(ebase + r) * H_ + col] = outv;
                shv[r * 256 + col] = outv;
            }
            __syncthreads();
        }

        // ---- phase 3: h1 = new_h @ W0T (K=256, staged smem) --------------
        float c0 = 0.f, c1 = 0.f;
        {
            for (int f = tid; f < 2048; f += 512) sW4[f] = w0t4[f];
            __syncthreads();
            #pragma unroll 1
            for (int c = 0; c < 8; c++) {
                if (c < 7) {
                    const float4* src = w0t4 + (c + 1) * 2048;
                    float4* dst = sW4 + ((c + 1) & 1) * 2048;
                    for (int f = tid; f < 2048; f += 512) dst[f] = src[f];
                }
                const float* wb = sW + (c & 1) * 8192;
                const float4* x0v = (const float4*)(shv + (half * 2 + 0) * 256 + c * 32);
                const float4* x1v = (const float4*)(shv + (half * 2 + 1) * 256 + c * 32);
                #pragma unroll
                for (int k4 = 0; k4 < 8; k4++) {
                    float w0 = wb[(k4 * 4 + 0) * 256 + col];
                    float w1 = wb[(k4 * 4 + 1) * 256 + col];
                    float w2 = wb[(k4 * 4 + 2) * 256 + col];
                    float w3 = wb[(k4 * 4 + 3) * 256 + col];
                    float4 xa = x0v[k4], xb = x1v[k4];
                    c0 += w0 * xa.x + w1 * xa.y + w2 * xa.z + w3 * xa.w;
                    c1 += w0 * xb.x + w1 * xb.y + w2 * xb.z + w3 * xb.w;
                }
                __syncthreads();
            }
        }
        {
            float y[2];
            float accv[2] = {c0, c1};
            #pragma unroll
            for (int rr = 0; rr < 2; rr++) {
                int r = half * 2 + rr;
                y[rr] = accv[rr] + bias0;
                float v = (col == 0) ? 0.f : y[rr] * y[rr];
                #pragma unroll
                for (int o = 16; o > 0; o >>= 1) v += __shfl_down_sync(0xffffffffu, v, o);
                if (lane == 0) redsh[r][warp & 7] = v;
                if (col == 0) ybc[r] = y[rr];
            }
            __syncthreads();
            #pragma unroll
            for (int rr = 0; rr < 2; rr++) {
                int r = half * 2 + rr;
                float ss = 0.f;
                #pragma unroll
                for (int w8 = 0; w8 < 8; w8++) ss += redsh[r][w8];
                float time = e_s0 / (1.f + expf(-ybc[r])) + 1.1f;
                float sc = sqrtf((time * time - 1.f) / fmaxf(ss, 1e-8f));
                g_h1buf[(ebase + r) * H_ + col] = (col == 0) ? time : y[rr] * sc;
            }
        }

        // ---- grid barrier -------------------------------------------------
        __threadfence();
        __syncthreads();
        if (tid == 0) {
            atomicAdd((int*)&g_bar[t], 1);
            while (g_bar[t] < NB_) __nanosleep(64);
        }
        __syncthreads();
    }
}

// ------------------------- build X rows for centroid GEMM ----------------
__global__ void xbuild(const int* __restrict__ bidx, const float* __restrict__ xtv) {
    int row = blockIdx.x, tid = threadIdx.x;  // 384 threads
    float v = 0.f;
    if (row < E_) {
        const float* ctx = xtv + bidx[row] * L_;
        if (tid == 0) {
            float n0 = g_hbuf[row * H_];
            float c0 = ctx[0];
            v = sqrtf(fmaxf(n0 * n0 + c0 * c0 - 1.f, 1e-8f));
        } else if (tid < H_) v = g_hbuf[row * H_ + tid];
        else if (tid < DC_)  v = ctx[tid - 255];
    } else {
        const float* ctx = xtv + (row - E_) * L_;
        if (tid == 0) v = sqrtf(fmaxf(ctx[0] * ctx[0], 1e-8f));
        else if (tid >= H_ && tid < DC_) v = ctx[tid - 255];
    }
    g_X[row * 384 + tid] = v;
}

// -------------- fused centroid scores GEMM + softmax CE + argmax ----------
__global__ void __launch_bounds__(256) scores_ce_kernel(
    const float* __restrict__ wbias,
    const int*   __restrict__ dir,
    const int*   __restrict__ ptg,
    const int*   __restrict__ rwid) {
    extern __shared__ float dsm[];
    float* xs  = dsm;                // [16][384]
    float* scr = dsm + 16 * 384;     // [16][788]
    int rb = blockIdx.x * 16, tid = threadIdx.x;
    for (int idx = tid; idx < 16 * 384; idx += 256) xs[idx] = g_X[rb * 384 + idx];
    __syncthreads();

    for (int cc = 0; cc < 4; cc++) {
        int colv = cc * 256 + tid;
        if (colv < V_) {
            float acc[16];
            #pragma unroll
            for (int r = 0; r < 16; r++) acc[r] = 0.f;
            for (int i = 0; i < 384; i += 4) {
                float g0 = g_Gt[(i + 0) * V_ + colv];
                float g1 = g_Gt[(i + 1) * V_ + colv];
                float g2 = g_Gt[(i + 2) * V_ + colv];
                float g3 = g_Gt[(i + 3) * V_ + colv];
                #pragma unroll
                for (int r = 0; r < 16; r++) {
                    float4 xv = *(const float4*)&xs[r * 384 + i];
                    acc[r] += g0 * xv.x + g1 * xv.y + g2 * xv.z + g3 * xv.w;
                }
            }
            float bb = wbias[colv];
            #pragma unroll
            for (int r = 0; r < 16; r++)
                scr[r * 788 + colv] = 2.f + 2.f * acc[r] + bb;
        }
    }
    __syncthreads();

    int w = tid >> 5, lane = tid & 31;
    #pragma unroll
    for (int rr = 0; rr < 2; rr++) {
        int r = w * 2 + rr;
        int row = rb + r;
        const float* s = scr + r * 788;
        float mx = -1e30f; int mi = 0x7fffffff;
        for (int j = lane; j < V_; j += 32) {
            float v = s[j];
            if (v > mx) { mx = v; mi = j; }
        }
        #pragma unroll
        for (int o = 16; o > 0; o >>= 1) {
            float om = __shfl_down_sync(0xffffffffu, mx, o);
            int   oi = __shfl_down_sync(0xffffffffu, mi, o);
            if (om > mx || (om == mx && oi < mi)) { mx = om; mi = oi; }
        }
        mx = __shfl_sync(0xffffffffu, mx, 0);
        mi = __shfl_sync(0xffffffffu, mi, 0);
        float p = 0.f;
        for (int j = lane; j < V_; j += 32) p += __expf(s[j] - mx);
        #pragma unroll
        for (int o = 16; o > 0; o >>= 1) p += __shfl_down_sync(0xffffffffu, p, o);
        if (lane == 0) {
            float lse = mx + logf(p);
            if (row < E_) {
                float pm = (float)dir[row];
                int tgt = ptg[row];
                float ce = lse - s[tgt];
                atomicAdd(&g_acc[0], (double)(pm * ce));
                atomicAdd(&g_acc[1], (double)(pm * ((mi == tgt) ? 1.f : 0.f)));
                atomicAdd(&g_acc[2], (double)pm);
            } else {
                int tgt = rwid[row - E_];
                float ce = lse - s[tgt];
                atomicAdd(&g_acc[0], (double)ce);
                atomicAdd(&g_acc[1], (mi == tgt) ? 1.0 : 0.0);
            }
        }
    }
}

// ------------------------- stop head --------------------------------------
__global__ void stop_kernel(const int*   __restrict__ wid,
                            const int*   __restrict__ noi,
                            const float* __restrict__ now,
                            const int*   __restrict__ bidx,
                            const int*   __restrict__ dir,
                            const int*   __restrict__ rwid,
                            const int*   __restrict__ roi,
                            const float* __restrict__ row_w,
                            const float* __restrict__ xtv,
                            const float* __restrict__ emb,
                            const float* __restrict__ ucls,
                            const float* __restrict__ ubias) {
    int row = blockIdx.x, tid = threadIdx.x;
    __shared__ float red[32];
    int widx, tgt;
    const int* oidx; const float* ow; const float* ctx;
    if (row < E_) {
        widx = wid[row]; tgt = dir[row];
        oidx = noi + row * K_; ow = now + row * K_;
        ctx = xtv + bidx[row] * L_;
    } else {
        int b = row - E_;
        widx = rwid[b]; tgt = 0;
        oidx = roi + b * K_; ow = row_w + b * K_;
        ctx = xtv + b * L_;
    }
    float wsum = 0.f, a = 0.f;
    #pragma unroll
    for (int k = 0; k < K_; k++) {
        int id = oidx[k]; float w = ow[k];
        wsum += w;
        a += w * g_hbuf[id * H_ + tid];
    }
    a /= fmaxf(wsum, 1e-8f);
    float inner = blockReduceSum((tid == 0) ? -a * a : a * a, red);
    float co = a / sqrtf(fmaxf(-inner, 1e-8f));
    float cx = emb[widx * H_ + tid];
    float d0, d1;
    if (tid == 0) {
        float t2s = fmaxf(cx * cx + co * co - 1.f, 1e-8f);
        float c0 = ctx[0];
        float x0 = sqrtf(fmaxf(t2s + c0 * c0 - 1.f, 1e-8f));
        d0 = -x0 * ucls[0];
        d1 = -x0 * ucls[DS_];
    } else {
        d0 = cx * ucls[tid] + co * ucls[255 + tid];
        d1 = cx * ucls[DS_ + tid] + co * ucls[DS_ + 255 + tid];
        if (tid < L_) {
            float cv = ctx[tid];
            d0 += cv * ucls[510 + tid];
            d1 += cv * ucls[DS_ + 510 + tid];
        }
    }
    float sc0 = blockReduceSum(d0, red);
    float sc1 = blockReduceSum(d1, red);
    if (tid == 0) {
        sc0 = 2.f + 2.f * sc0 + ubias[0];
        sc1 = 2.f + 2.f * sc1 + ubias[1];
        float mxv = fmaxf(sc0, sc1);
        float lse = mxv + logf(expf(sc0 - mxv) + expf(sc1 - mxv));
        float ce = lse - ((tgt == 0) ? sc0 : sc1);
        int am = (sc1 > sc0) ? 1 : 0;
        atomicAdd(&g_acc[3], (double)ce);
        atomicAdd(&g_acc[4], (am == tgt) ? 1.0 : 0.0);
    }
}

// ------------------------- finalize ---------------------------------------
__global__ void finalize(float* __restrict__ out) {
    out[0] = (float)(g_acc[0] / (double)B_);
    out[1] = (float)(g_acc[3] / (double)B_);
    out[2] = (float)(g_acc[1] / ((double)B_ + g_acc[2]));
    out[3] = (float)(g_acc[4] / (double)(E_ + B_));
}

// ------------------------- launch ------------------------------------------
extern "C" void kernel_launch(void* const* d_in, const int* in_sizes, int n_in,
                              void* d_out, int out_size) {
    const int*   wid   = (const int*)  d_in[0];
    const int*   nhi   = (const int*)  d_in[1];
    const float* nhw   = (const float*)d_in[2];
    const int*   noi   = (const int*)  d_in[3];
    const float* now_  = (const float*)d_in[4];
    const int*   bidx  = (const int*)  d_in[5];
    const int*   dir   = (const int*)  d_in[6];
    const int*   ptg   = (const int*)  d_in[7];
    const int*   rwid  = (const int*)  d_in[8];
    const int*   roi   = (const int*)  d_in[9];
    const float* row_w = (const float*)d_in[10];
    const float* xtv   = (const float*)d_in[11];
    const float* emb   = (const float*)d_in[12];
    const float* W0    = (const float*)d_in[13];
    const float* b0    = (const float*)d_in[14];
    const float* s0    = (const float*)d_in[15];
    const float* W1    = (const float*)d_in[16];
    const float* b1    = (const float*)d_in[17];
    const float* s1    = (const float*)d_in[18];
    const float* wcls  = (const float*)d_in[19];
    const float* wbias = (const float*)d_in[20];
    const float* ucls  = (const float*)d_in[21];
    const float* ubias = (const float*)d_in[22];
    float* out = (float*)d_out;

    const int smem_ce   = (16 * 384 + 16 * 788) * sizeof(float);   // ~75 KB
    const int smem_scan = (16384 + 1024 + 1024) * sizeof(float);   // 73728 B
    cudaFuncSetAttribute(scores_ce_kernel,
                         cudaFuncAttributeMaxDynamicSharedMemorySize, smem_ce);
    cudaFuncSetAttribute(scan_kernel,
                         cudaFuncAttributeMaxDynamicSharedMemorySize, smem_scan);

    prep_misc<<<1024, 256>>>(W0, W1, wcls);
    prep_pad<<<1, 256>>>(W0, b0, s0);
    prep_embW1<<<(V_ + 15) / 16, 256>>>(emb);
    scan_kernel<<<NB_, 512, smem_scan>>>(wid, nhi, nhw, emb, b0, s0, b1, s1);
    xbuild<<<NROWS, 384>>>(bidx, xtv);
    scores_ce_kernel<<<NROWS / 16, 256, smem_ce>>>(wbias, dir, ptg, rwid);
    stop_kernel<<<NROWS, 256>>>(wid, noi, now_, bidx, dir, rwid, roi, row_w,
                                xtv, emb, ucls, ubias);
    finalize<<<1, 1>>>(out);
}

// round 7
// speedup vs baseline: 1.4770x; 1.4770x over previous
#include <cuda_runtime.h>
#include <math.h>

#define T_ 64
#define M_ 256
#define K_ 6
#define B_ 256
#define H_ 256
#define L_ 128
#define V_ 780
#define E_ 16384
#define DC_ 383          // wcls cols = H+L-1
#define DS_ 638          // ucls cols = 2H+L-2
#define NROWS (E_ + B_)  // msg rows + root rows
#define NB_ 64           // scan blocks (must all be resident)

// ------------------------- device scratch --------------------------------
__device__ __align__(16) float  g_hbuf [(E_ + 1) * H_];
__device__ __align__(16) float  g_h1buf[(E_ + 1) * H_];
__device__ __align__(16) float  g_W1T  [512 * H_];      // full W1^T (for embW1 prep)
__device__ __align__(16) float  g_W1B  [H_ * H_];       // row0=W1[:,0], rowk=W1[:,255+k]
__device__ __align__(16) float  g_W0T  [H_ * H_];
__device__ __align__(16) float  g_embW1[V_ * H_];       // emb_spatial @ W1^T_spatial
__device__ __align__(16) float  g_Gt   [384 * V_];
__device__ __align__(16) float  g_X    [NROWS * 384];
__device__ double g_acc[6];
__device__ volatile int g_bar[T_];

// ------------------------- helpers ---------------------------------------
__device__ __forceinline__ float blockReduceSum(float v, float* sh) {
    __syncthreads();
    #pragma unroll
    for (int o = 16; o > 0; o >>= 1) v += __shfl_down_sync(0xffffffffu, v, o);
    int tid = threadIdx.x;
    if ((tid & 31) == 0) sh[tid >> 5] = v;
    __syncthreads();
    if (tid < 32) {
        int nw = (blockDim.x + 31) >> 5;
        v = (tid < nw) ? sh[tid] : 0.f;
        #pragma unroll
        for (int o = 16; o > 0; o >>= 1) v += __shfl_down_sync(0xffffffffu, v, o);
        if (tid == 0) sh[0] = v;
    }
    __syncthreads();
    return sh[0];
}

// ------------------------- prep -------------------------------------------
__global__ void prep_misc(const float* __restrict__ W0,
                          const float* __restrict__ W1,
                          const float* __restrict__ wcls) {
    if (blockIdx.x == 0 && threadIdx.x < T_) g_bar[threadIdx.x] = 0;
    const int n1 = 512 * H_;        // W1T
    const int n2 = H_ * H_;         // W0T
    const int n3 = 384 * V_;        // Gt
    const int n4 = H_ * H_;         // W1B
    for (int idx = blockIdx.x * blockDim.x + threadIdx.x;
         idx < n1 + n2 + n3 + n4; idx += gridDim.x * blockDim.x) {
        if (idx < n1) {
            int i = idx >> 8, j = idx & 255;
            g_W1T[idx] = (i < 511) ? W1[j * 511 + i] : 0.f;
        } else if (idx < n1 + n2) {
            int k = idx - n1;
            int i = k >> 8, j = k & 255;
            g_W0T[k] = W0[j * H_ + i];
        } else if (idx < n1 + n2 + n3) {
            int k = idx - n1 - n2;
            int i = k / V_, v = k % V_;
            float g;
            if (i == 0)       g = -wcls[v * DC_];
            else if (i < DC_) g = wcls[v * DC_ + i];
            else              g = 0.f;
            g_Gt[k] = g;
        } else {
            int k = idx - n1 - n2 - n3;
            int i = k >> 8, j = k & 255;    // W1B[i][j]
            g_W1B[k] = (i == 0) ? W1[j * 511] : W1[j * 511 + 255 + i];
        }
    }
}

__global__ void prep_pad(const float* __restrict__ W0,
                         const float* __restrict__ b0,
                         const float* __restrict__ s0p) {
    __shared__ float red[32];
    __shared__ float ybc;
    int tid = threadIdx.x;
    if (tid < 6) g_acc[tid] = 0.0;
    g_hbuf[E_ * H_ + tid] = (tid == 0) ? 1.f : 0.f;
    float y = W0[tid * H_] + b0[tid];
    if (tid == 0) ybc = y;
    float ss = blockReduceSum((tid == 0) ? 0.f : y * y, red);
    float time = expf(s0p[0]) / (1.f + expf(-ybc)) + 1.1f;
    float sc = sqrtf((time * time - 1.f) / fmaxf(ss, 1e-8f));
    g_h1buf[E_ * H_ + tid] = (tid == 0) ? time : y * sc;
}

// embW1[v][j] = sum_{i=1..255} emb[v][i] * W1T[i][j]   (16 v-rows per block)
__global__ void prep_embW1(const float* __restrict__ emb) {
    __shared__ float es[16][256];
    int v0 = blockIdx.x * 16, tid = threadIdx.x;
    for (int i = tid; i < 16 * 256; i += 256) {
        int r = i >> 8, c = i & 255;
        es[r][c] = (v0 + r < V_) ? emb[(v0 + r) * H_ + c] : 0.f;
    }
    __syncthreads();
    float acc[16];
    #pragma unroll
    for (int r = 0; r < 16; r++) acc[r] = 0.f;
    for (int i = 1; i < 256; i++) {
        float w = g_W1T[i * H_ + tid];
        #pragma unroll
        for (int r = 0; r < 16; r++) acc[r] += es[r][i] * w;
    }
    #pragma unroll
    for (int r = 0; r < 16; r++)
        if (v0 + r < V_) g_embW1[(v0 + r) * H_ + tid] = acc[r];
}

// ------------------------- persistent scan kernel -------------------------
// 64 blocks x 512 threads (R5 structure). col = tid&255, half = tid>>8.
// Phase1: each half builds 2 rows. GEMMs: K split across halves (part[] reduce).
__global__ void __launch_bounds__(512, 1) scan_kernel(
    const int*   __restrict__ wid,
    const int*   __restrict__ nhi,
    const float* __restrict__ nhw,
    const float* __restrict__ emb,
    const float* __restrict__ b0,
    const float* __restrict__ s0p,
    const float* __restrict__ b1,
    const float* __restrict__ s1p) {
    __shared__ float svec[4][256];   // [x0, h1m_spatial(1..255)]
    __shared__ float shv [4][256];   // new_h rows
    __shared__ float part[4][512];
    __shared__ float redsh[4][8];
    __shared__ float ybc[4];

    int tid  = threadIdx.x;
    int col  = tid & 255;
    int half = tid >> 8;
    int warp = tid >> 5;
    int lane = tid & 31;
    int bx   = blockIdx.x;
    float e_s0 = expf(s0p[0]);
    float e_s1 = expf(s1p[0]);
    float bias1 = b1[col];
    float bias0 = b0[col];

    for (int t = 0; t < T_; t++) {
        int ebase = t * M_ + bx * 4;

        // ---- phase 1: gathered midpoint on h1buf, build svec -------------
        #pragma unroll
        for (int rr = 0; rr < 2; rr++) {
            int r = half * 2 + rr;
            int e = ebase + r;
            float wsum = 0.f, a = 0.f;
            #pragma unroll
            for (int k = 0; k < K_; k++) {
                int   id = nhi[e * K_ + k];
                float w  = nhw[e * K_ + k];
                wsum += w;
                a += w * g_h1buf[id * H_ + col];
            }
            a /= fmaxf(wsum, 1e-8f);
            float v = (col == 0) ? a * a : -a * a;   // time^2 - |spatial|^2
            #pragma unroll
            for (int o = 16; o > 0; o >>= 1) v += __shfl_down_sync(0xffffffffu, v, o);
            if (lane == 0) redsh[r][warp & 7] = v;
            __syncthreads();
            float inn = 0.f;
            #pragma unroll
            for (int w8 = 0; w8 < 8; w8++) inn += redsh[r][w8];
            float h1m = a / sqrtf(fmaxf(inn, 1e-8f));
            if (col == 0) {
                float cx0 = emb[wid[e] * H_];
                svec[r][0] = sqrtf(fmaxf(cx0 * cx0 + h1m * h1m - 1.0f, 1e-8f));
            } else {
                svec[r][col] = h1m;
            }
        }
        __syncthreads();

        // ---- phase 2: Y = svec @ W1B (K=256, split across halves) --------
        float a0 = 0.f, a1 = 0.f, a2 = 0.f, a3 = 0.f;
        {
            const float*  wp  = g_W1B + (half * 128) * H_ + col;
            const float4* s0v = (const float4*)&svec[0][half * 128];
            const float4* s1v = (const float4*)&svec[1][half * 128];
            const float4* s2v = (const float4*)&svec[2][half * 128];
            const float4* s3v = (const float4*)&svec[3][half * 128];
            #pragma unroll 8
            for (int i4 = 0; i4 < 32; i4++) {
                int base = (i4 * 4) * H_;
                float w0 = wp[base], w1 = wp[base + H_];
                float w2 = wp[base + 2 * H_], w3 = wp[base + 3 * H_];
                float4 x0 = s0v[i4], x1 = s1v[i4], x2 = s2v[i4], x3 = s3v[i4];
                a0 += w0 * x0.x + w1 * x0.y + w2 * x0.z + w3 * x0.w;
                a1 += w0 * x1.x + w1 * x1.y + w2 * x1.z + w3 * x1.w;
                a2 += w0 * x2.x + w1 * x2.y + w2 * x2.z + w3 * x2.w;
                a3 += w0 * x3.x + w1 * x3.y + w2 * x3.z + w3 * x3.w;
            }
        }
        part[0][tid] = a0; part[1][tid] = a1; part[2][tid] = a2; part[3][tid] = a3;
        __syncthreads();

        float y[4];
        if (half == 0) {
            #pragma unroll
            for (int r = 0; r < 4; r++) {
                int e = ebase + r;
                y[r] = part[r][col] + part[r][256 + col] + bias1
                     + g_embW1[wid[e] * H_ + col];
                float v = (col == 0) ? 0.f : y[r] * y[r];
                #pragma unroll
                for (int o = 16; o > 0; o >>= 1) v += __shfl_down_sync(0xffffffffu, v, o);
                if (lane == 0) redsh[r][warp] = v;
                if (col == 0) ybc[r] = y[r];
            }
        }
        __syncthreads();
        if (half == 0) {
            #pragma unroll
            for (int r = 0; r < 4; r++) {
                float ss = 0.f;
                #pragma unroll
                for (int w8 = 0; w8 < 8; w8++) ss += redsh[r][w8];
                float time = e_s1 / (1.f + expf(-ybc[r])) + 1.1f;
                float sc = sqrtf((time * time - 1.f) / fmaxf(ss, 1e-8f));
                float outv = (col == 0) ? time : y[r] * sc;
                g_hbuf[(ebase + r) * H_ + col] = outv;
                shv[r][col] = outv;
            }
        }
        __syncthreads();

        // ---- phase 3: h1 = new_h @ W0T (K=256, split across halves) ------
        float c0 = 0.f, c1 = 0.f, c2 = 0.f, c3 = 0.f;
        {
            const float*  wp  = g_W0T + (half * 128) * H_ + col;
            const float4* s0v = (const float4*)&shv[0][half * 128];
            const float4* s1v = (const float4*)&shv[1][half * 128];
            const float4* s2v = (const float4*)&shv[2][half * 128];
            const float4* s3v = (const float4*)&shv[3][half * 128];
            #pragma unroll 8
            for (int i4 = 0; i4 < 32; i4++) {
                int base = (i4 * 4) * H_;
                float w0 = wp[base], w1 = wp[base + H_];
                float w2 = wp[base + 2 * H_], w3 = wp[base + 3 * H_];
                float4 x0 = s0v[i4], x1 = s1v[i4], x2 = s2v[i4], x3 = s3v[i4];
                c0 += w0 * x0.x + w1 * x0.y + w2 * x0.z + w3 * x0.w;
                c1 += w0 * x1.x + w1 * x1.y + w2 * x1.z + w3 * x1.w;
                c2 += w0 * x2.x + w1 * x2.y + w2 * x2.z + w3 * x2.w;
                c3 += w0 * x3.x + w1 * x3.y + w2 * x3.z + w3 * x3.w;
            }
        }
        part[0][tid] = c0; part[1][tid] = c1; part[2][tid] = c2; part[3][tid] = c3;
        __syncthreads();

        if (half == 0) {
            #pragma unroll
            for (int r = 0; r < 4; r++) {
                y[r] = part[r][col] + part[r][256 + col] + bias0;
                float v = (col == 0) ? 0.f : y[r] * y[r];
                #pragma unroll
                for (int o = 16; o > 0; o >>= 1) v += __shfl_down_sync(0xffffffffu, v, o);
                if (lane == 0) redsh[r][warp] = v;
                if (col == 0) ybc[r] = y[r];
            }
        }
        __syncthreads();
        if (half == 0) {
            #pragma unroll
            for (int r = 0; r < 4; r++) {
                float ss = 0.f;
                #pragma unroll
                for (int w8 = 0; w8 < 8; w8++) ss += redsh[r][w8];
                float time = e_s0 / (1.f + expf(-ybc[r])) + 1.1f;
                float sc = sqrtf((time * time - 1.f) / fmaxf(ss, 1e-8f));
                g_h1buf[(ebase + r) * H_ + col] = (col == 0) ? time : y[r] * sc;
            }
        }

        // ---- grid barrier (release h1buf writes of step t) ---------------
        __threadfence();
        __syncthreads();
        if (tid == 0) {
            atomicAdd((int*)&g_bar[t], 1);
            while (g_bar[t] < NB_) __nanosleep(64);
        }
        __syncthreads();
    }
}

// ------------------------- build X rows for centroid GEMM ----------------
__global__ void xbuild(const int* __restrict__ bidx, const float* __restrict__ xtv) {
    int row = blockIdx.x, tid = threadIdx.x;  // 384 threads
    float v = 0.f;
    if (row < E_) {
        const float* ctx = xtv + bidx[row] * L_;
        if (tid == 0) {
            float n0 = g_hbuf[row * H_];
            float c0 = ctx[0];
            v = sqrtf(fmaxf(n0 * n0 + c0 * c0 - 1.f, 1e-8f));
        } else if (tid < H_) v = g_hbuf[row * H_ + tid];
        else if (tid < DC_)  v = ctx[tid - 255];
    } else {
        const float* ctx = xtv + (row - E_) * L_;
        if (tid == 0) v = sqrtf(fmaxf(ctx[0] * ctx[0], 1e-8f));
        else if (tid >= H_ && tid < DC_) v = ctx[tid - 255];
    }
    g_X[row * 384 + tid] = v;
}

// -------------- fused centroid scores GEMM + softmax CE + argmax ----------
__global__ void __launch_bounds__(256) scores_ce_kernel(
    const float* __restrict__ wbias,
    const int*   __restrict__ dir,
    const int*   __restrict__ ptg,
    const int*   __restrict__ rwid) {
    extern __shared__ float dsm[];
    float* xs  = dsm;                // [16][384]
    float* scr = dsm + 16 * 384;     // [16][788]
    int rb = blockIdx.x * 16, tid = threadIdx.x;
    for (int idx = tid; idx < 16 * 384; idx += 256) xs[idx] = g_X[rb * 384 + idx];
    __syncthreads();

    for (int cc = 0; cc < 4; cc++) {
        int colv = cc * 256 + tid;
        if (colv < V_) {
            float acc[16];
            #pragma unroll
            for (int r = 0; r < 16; r++) acc[r] = 0.f;
            for (int i = 0; i < 384; i += 4) {
                float g0 = g_Gt[(i + 0) * V_ + colv];
                float g1 = g_Gt[(i + 1) * V_ + colv];
                float g2 = g_Gt[(i + 2) * V_ + colv];
                float g3 = g_Gt[(i + 3) * V_ + colv];
                #pragma unroll
                for (int r = 0; r < 16; r++) {
                    float4 xv = *(const float4*)&xs[r * 384 + i];
                    acc[r] += g0 * xv.x + g1 * xv.y + g2 * xv.z + g3 * xv.w;
                }
            }
            float bb = wbias[colv];
            #pragma unroll
            for (int r = 0; r < 16; r++)
                scr[r * 788 + colv] = 2.f + 2.f * acc[r] + bb;
        }
    }
    __syncthreads();

    int w = tid >> 5, lane = tid & 31;
    #pragma unroll
    for (int rr = 0; rr < 2; rr++) {
        int r = w * 2 + rr;
        int row = rb + r;
        const float* s = scr + r * 788;
        float mx = -1e30f; int mi = 0x7fffffff;
        for (int j = lane; j < V_; j += 32) {
            float v = s[j];
            if (v > mx) { mx = v; mi = j; }
        }
        #pragma unroll
        for (int o = 16; o > 0; o >>= 1) {
            float om = __shfl_down_sync(0xffffffffu, mx, o);
            int   oi = __shfl_down_sync(0xffffffffu, mi, o);
            if (om > mx || (om == mx && oi < mi)) { mx = om; mi = oi; }
        }
        mx = __shfl_sync(0xffffffffu, mx, 0);
        mi = __shfl_sync(0xffffffffu, mi, 0);
        float p = 0.f;
        for (int j = lane; j < V_; j += 32) p += __expf(s[j] - mx);
        #pragma unroll
        for (int o = 16; o > 0; o >>= 1) p += __shfl_down_sync(0xffffffffu, p, o);
        if (lane == 0) {
            float lse = mx + logf(p);
            if (row < E_) {
                float pm = (float)dir[row];
                int tgt = ptg[row];
                float ce = lse - s[tgt];
                atomicAdd(&g_acc[0], (double)(pm * ce));
                atomicAdd(&g_acc[1], (double)(pm * ((mi == tgt) ? 1.f : 0.f)));
                atomicAdd(&g_acc[2], (double)pm);
            } else {
                int tgt = rwid[row - E_];
                float ce = lse - s[tgt];
                atomicAdd(&g_acc[0], (double)ce);
                atomicAdd(&g_acc[1], (mi == tgt) ? 1.0 : 0.0);
            }
        }
    }
}

// ------------------------- stop head --------------------------------------
__global__ void stop_kernel(const int*   __restrict__ wid,
                            const int*   __restrict__ noi,
                            const float* __restrict__ now,
                            const int*   __restrict__ bidx,
                            const int*   __restrict__ dir,
                            const int*   __restrict__ rwid,
                            const int*   __restrict__ roi,
                            const float* __restrict__ row_w,
                            const float* __restrict__ xtv,
                            const float* __restrict__ emb,
                            const float* __restrict__ ucls,
                            const float* __restrict__ ubias) {
    int row = blockIdx.x, tid = threadIdx.x;
    __shared__ float red[32];
    int widx, tgt;
    const int* oidx; const float* ow; const float* ctx;
    if (row < E_) {
        widx = wid[row]; tgt = dir[row];
        oidx = noi + row * K_; ow = now + row * K_;
        ctx = xtv + bidx[row] * L_;
    } else {
        int b = row - E_;
        widx = rwid[b]; tgt = 0;
        oidx = roi + b * K_; ow = row_w + b * K_;
        ctx = xtv + b * L_;
    }
    float wsum = 0.f, a = 0.f;
    #pragma unroll
    for (int k = 0; k < K_; k++) {
        int id = oidx[k]; float w = ow[k];
        wsum += w;
        a += w * g_hbuf[id * H_ + tid];
    }
    a /= fmaxf(wsum, 1e-8f);
    float inner = blockReduceSum((tid == 0) ? -a * a : a * a, red);
    float co = a / sqrtf(fmaxf(-inner, 1e-8f));
    float cx = emb[widx * H_ + tid];
    float d0, d1;
    if (tid == 0) {
        float t2s = fmaxf(cx * cx + co * co - 1.f, 1e-8f);
        float c0 = ctx[0];
        float x0 = sqrtf(fmaxf(t2s + c0 * c0 - 1.f, 1e-8f));
        d0 = -x0 * ucls[0];
        d1 = -x0 * ucls[DS_];
    } else {
        d0 = cx * ucls[tid] + co * ucls[255 + tid];
        d1 = cx * ucls[DS_ + tid] + co * ucls[DS_ + 255 + tid];
        if (tid < L_) {
            float cv = ctx[tid];
            d0 += cv * ucls[510 + tid];
            d1 += cv * ucls[DS_ + 510 + tid];
        }
    }
    float sc0 = blockReduceSum(d0, red);
    float sc1 = blockReduceSum(d1, red);
    if (tid == 0) {
        sc0 = 2.f + 2.f * sc0 + ubias[0];
        sc1 = 2.f + 2.f * sc1 + ubias[1];
        float mxv = fmaxf(sc0, sc1);
        float lse = mxv + logf(expf(sc0 - mxv) + expf(sc1 - mxv));
        float ce = lse - ((tgt == 0) ? sc0 : sc1);
        int am = (sc1 > sc0) ? 1 : 0;
        atomicAdd(&g_acc[3], (double)ce);
        atomicAdd(&g_acc[4], (am == tgt) ? 1.0 : 0.0);
    }
}

// ------------------------- finalize ---------------------------------------
__global__ void finalize(float* __restrict__ out) {
    out[0] = (float)(g_acc[0] / (double)B_);
    out[1] = (float)(g_acc[3] / (double)B_);
    out[2] = (float)(g_acc[1] / ((double)B_ + g_acc[2]));
    out[3] = (float)(g_acc[4] / (double)(E_ + B_));
}

// ------------------------- launch ------------------------------------------
extern "C" void kernel_launch(void* const* d_in, const int* in_sizes, int n_in,
                              void* d_out, int out_size) {
    const int*   wid   = (const int*)  d_in[0];
    const int*   nhi   = (const int*)  d_in[1];
    const float* nhw   = (const float*)d_in[2];
    const int*   noi   = (const int*)  d_in[3];
    const float* now_  = (const float*)d_in[4];
    const int*   bidx  = (const int*)  d_in[5];
    const int*   dir   = (const int*)  d_in[6];
    const int*   ptg   = (const int*)  d_in[7];
    const int*   rwid  = (const int*)  d_in[8];
    const int*   roi   = (const int*)  d_in[9];
    const float* row_w = (const float*)d_in[10];
    const float* xtv   = (const float*)d_in[11];
    const float* emb   = (const float*)d_in[12];
    const float* W0    = (const float*)d_in[13];
    const float* b0    = (const float*)d_in[14];
    const float* s0    = (const float*)d_in[15];
    const float* W1    = (const float*)d_in[16];
    const float* b1    = (const float*)d_in[17];
    const float* s1    = (const float*)d_in[18];
    const float* wcls  = (const float*)d_in[19];
    const float* wbias = (const float*)d_in[20];
    const float* ucls  = (const float*)d_in[21];
    const float* ubias = (const float*)d_in[22];
    float* out = (float*)d_out;

    const int smem_ce = (16 * 384 + 16 * 788) * sizeof(float);  // ~75 KB
    cudaFuncSetAttribute(scores_ce_kernel,
                         cudaFuncAttributeMaxDynamicSharedMemorySize, smem_ce);

    prep_misc<<<1024, 256>>>(W0, W1, wcls);
    prep_pad<<<1, 256>>>(W0, b0, s0);
    prep_embW1<<<(V_ + 15) / 16, 256>>>(emb);
    scan_kernel<<<NB_, 512>>>(wid, nhi, nhw, emb, b0, s0, b1, s1);
    xbuild<<<NROWS, 384>>>(bidx, xtv);
    scores_ce_kernel<<<NROWS / 16, 256, smem_ce>>>(wbias, dir, ptg, rwid);
    stop_kernel<<<NROWS, 256>>>(wid, noi, now_, bidx, dir, rwid, roi, row_w,
                                xtv, emb, ucls, ubias);
    finalize<<<1, 1>>>(out);
}

// round 8
// speedup vs baseline: 1.7792x; 1.2046x over previous
#include <cuda_runtime.h>
#include <math.h>

#define T_ 64
#define M_ 256
#define K_ 6
#define B_ 256
#define H_ 256
#define L_ 128
#define V_ 780
#define E_ 16384
#define DC_ 383          // wcls cols = H+L-1
#define DS_ 638          // ucls cols = 2H+L-2
#define NROWS (E_ + B_)  // msg rows + root rows
#define NB_ 64           // scan blocks (must all be resident)

// ------------------------- device scratch --------------------------------
__device__ __align__(16) float  g_hbuf [(E_ + 1) * H_];
__device__ __align__(16) float  g_h1buf[(E_ + 1) * H_];
__device__ __align__(16) float  g_W1T  [512 * H_];      // for embW1 prep
__device__ __align__(16) float  g_W1P  [H_ * H_];       // packed: [(k>>2)*256+col]*4+(k&3)
__device__ __align__(16) float  g_W0P  [H_ * H_];       // packed W0^T
__device__ __align__(16) float  g_embW1[V_ * H_];       // emb_spatial @ W1^T_spatial
__device__ __align__(16) float  g_Gt   [384 * V_];      // full centroid matrix (scalar)
__device__ __align__(16) float  g_GtP  [256 * V_];      // packed rows 0..255: [(i>>2)*V+v]*4+(i&3)
__device__ __align__(16) float  g_ctxG [B_ * V_];       // ctx_spatial(b) . Gt[256..382]
__device__ __align__(16) float  g_X    [NROWS * H_];    // [x0, h_spatial]
__device__ double g_acc[6];
__device__ volatile int g_bar[T_];

// ------------------------- helpers ---------------------------------------
__device__ __forceinline__ float blockReduceSum(float v, float* sh) {
    __syncthreads();
    #pragma unroll
    for (int o = 16; o > 0; o >>= 1) v += __shfl_down_sync(0xffffffffu, v, o);
    int tid = threadIdx.x;
    if ((tid & 31) == 0) sh[tid >> 5] = v;
    __syncthreads();
    if (tid < 32) {
        int nw = (blockDim.x + 31) >> 5;
        v = (tid < nw) ? sh[tid] : 0.f;
        #pragma unroll
        for (int o = 16; o > 0; o >>= 1) v += __shfl_down_sync(0xffffffffu, v, o);
        if (tid == 0) sh[0] = v;
    }
    __syncthreads();
    return sh[0];
}

__device__ __forceinline__ float gt_val(int i, int v, const float* wcls) {
    if (i == 0)  return -wcls[v * DC_];
    if (i < DC_) return wcls[v * DC_ + i];
    return 0.f;
}

// ------------------------- prep -------------------------------------------
__global__ void prep_misc(const float* __restrict__ W0,
                          const float* __restrict__ W1,
                          const float* __restrict__ wcls) {
    if (blockIdx.x == 0 && threadIdx.x < T_) g_bar[threadIdx.x] = 0;
    const int n1 = 512 * H_;        // W1T
    const int n2 = 384 * V_;        // Gt
    const int n3 = H_ * H_;         // W1P
    const int n4 = H_ * H_;         // W0P
    const int n5 = 256 * V_;        // GtP
    for (int idx = blockIdx.x * blockDim.x + threadIdx.x;
         idx < n1 + n2 + n3 + n4 + n5; idx += gridDim.x * blockDim.x) {
        if (idx < n1) {
            int i = idx >> 8, j = idx & 255;
            g_W1T[idx] = (i < 511) ? W1[j * 511 + i] : 0.f;
        } else if (idx < n1 + n2) {
            int k = idx - n1;
            int i = k / V_, v = k % V_;
            g_Gt[k] = gt_val(i, v, wcls);
        } else if (idx < n1 + n2 + n3) {
            int k = idx - n1 - n2;
            int i = k >> 8, j = k & 255;   // W1B row i, col j
            float val = (i == 0) ? W1[j * 511] : W1[j * 511 + 255 + i];
            g_W1P[((i >> 2) << 10) + (j << 2) + (i & 3)] = val;
        } else if (idx < n1 + n2 + n3 + n4) {
            int k = idx - n1 - n2 - n3;
            int i = k >> 8, j = k & 255;   // W0T row i, col j
            g_W0P[((i >> 2) << 10) + (j << 2) + (i & 3)] = W0[j * H_ + i];
        } else {
            int k = idx - n1 - n2 - n3 - n4;
            int i = k / V_, v = k % V_;    // rows 0..255
            g_GtP[(((i >> 2) * V_ + v) << 2) + (i & 3)] = gt_val(i, v, wcls);
        }
    }
}

__global__ void prep_pad(const float* __restrict__ W0,
                         const float* __restrict__ b0,
                         const float* __restrict__ s0p) {
    __shared__ float red[32];
    __shared__ float ybc;
    int tid = threadIdx.x;
    if (tid < 6) g_acc[tid] = 0.0;
    g_hbuf[E_ * H_ + tid] = (tid == 0) ? 1.f : 0.f;
    float y = W0[tid * H_] + b0[tid];
    if (tid == 0) ybc = y;
    float ss = blockReduceSum((tid == 0) ? 0.f : y * y, red);
    float time = expf(s0p[0]) / (1.f + expf(-ybc)) + 1.1f;
    float sc = sqrtf((time * time - 1.f) / fmaxf(ss, 1e-8f));
    g_h1buf[E_ * H_ + tid] = (tid == 0) ? time : y * sc;
}

// embW1[v][j] = sum_{i=1..255} emb[v][i] * W1T[i][j]
__global__ void prep_embW1(const float* __restrict__ emb) {
    __shared__ float es[16][256];
    int v0 = blockIdx.x * 16, tid = threadIdx.x;
    for (int i = tid; i < 16 * 256; i += 256) {
        int r = i >> 8, c = i & 255;
        es[r][c] = (v0 + r < V_) ? emb[(v0 + r) * H_ + c] : 0.f;
    }
    __syncthreads();
    float acc[16];
    #pragma unroll
    for (int r = 0; r < 16; r++) acc[r] = 0.f;
    for (int i = 1; i < 256; i++) {
        float w = g_W1T[i * H_ + tid];
        #pragma unroll
        for (int r = 0; r < 16; r++) acc[r] += es[r][i] * w;
    }
    #pragma unroll
    for (int r = 0; r < 16; r++)
        if (v0 + r < V_) g_embW1[(v0 + r) * H_ + tid] = acc[r];
}

// ctxG[b][v] = sum_{i=1..127} xtv[b][i] * Gt[255+i][v]
__global__ void prep_ctxG(const float* __restrict__ xtv) {
    __shared__ float cs[128];
    int b = blockIdx.x, tid = threadIdx.x;
    if (tid < 128) cs[tid] = xtv[b * L_ + tid];
    __syncthreads();
    for (int v = tid; v < V_; v += 256) {
        float acc = 0.f;
        for (int i = 1; i < 128; i++) acc += cs[i] * g_Gt[(255 + i) * V_ + v];
        g_ctxG[b * V_ + v] = acc;
    }
}

// ------------------------- persistent scan kernel -------------------------
// 64 blocks x 512 threads. col = tid&255, half = tid>>8.
// GEMMs: K split across halves, packed float4 weights (1 LDG.128 per 4 k).
__global__ void __launch_bounds__(512, 1) scan_kernel(
    const int*   __restrict__ wid,
    const int*   __restrict__ nhi,
    const float* __restrict__ nhw,
    const float* __restrict__ emb,
    const float* __restrict__ b0,
    const float* __restrict__ s0p,
    const float* __restrict__ b1,
    const float* __restrict__ s1p) {
    __shared__ float svec[4][256];
    __shared__ float shv [4][256];
    __shared__ float part[4][512];
    __shared__ float redsh[4][8];
    __shared__ float ybc[4];

    int tid  = threadIdx.x;
    int col  = tid & 255;
    int half = tid >> 8;
    int warp = tid >> 5;
    int lane = tid & 31;
    int bx   = blockIdx.x;
    float e_s0 = expf(s0p[0]);
    float e_s1 = expf(s1p[0]);
    float bias1 = b1[col];
    float bias0 = b0[col];

    const float4* w1p = (const float4*)g_W1P + half * 32 * 256 + col;
    const float4* w0p = (const float4*)g_W0P + half * 32 * 256 + col;

    for (int t = 0; t < T_; t++) {
        int ebase = t * M_ + bx * 4;

        // ---- phase 1: gathered midpoint on h1buf, build svec -------------
        #pragma unroll
        for (int rr = 0; rr < 2; rr++) {
            int r = half * 2 + rr;
            int e = ebase + r;
            float wsum = 0.f, a = 0.f;
            #pragma unroll
            for (int k = 0; k < K_; k++) {
                int   id = nhi[e * K_ + k];
                float w  = nhw[e * K_ + k];
                wsum += w;
                a += w * g_h1buf[id * H_ + col];
            }
            a /= fmaxf(wsum, 1e-8f);
            float v = (col == 0) ? a * a : -a * a;
            #pragma unroll
            for (int o = 16; o > 0; o >>= 1) v += __shfl_down_sync(0xffffffffu, v, o);
            if (lane == 0) redsh[r][warp & 7] = v;
            __syncthreads();
            float inn = 0.f;
            #pragma unroll
            for (int w8 = 0; w8 < 8; w8++) inn += redsh[r][w8];
            float h1m = a / sqrtf(fmaxf(inn, 1e-8f));
            if (col == 0) {
                float cx0 = emb[wid[e] * H_];
                svec[r][0] = sqrtf(fmaxf(cx0 * cx0 + h1m * h1m - 1.0f, 1e-8f));
            } else {
                svec[r][col] = h1m;
            }
        }
        __syncthreads();

        // ---- phase 2: Y = svec @ W1 (K=256, halves, packed float4) -------
        float a0 = 0.f, a1 = 0.f, a2 = 0.f, a3 = 0.f;
        {
            const float4* s0v = (const float4*)&svec[0][half * 128];
            const float4* s1v = (const float4*)&svec[1][half * 128];
            const float4* s2v = (const float4*)&svec[2][half * 128];
            const float4* s3v = (const float4*)&svec[3][half * 128];
            #pragma unroll 8
            for (int i4 = 0; i4 < 32; i4++) {
                float4 w = w1p[i4 * 256];
                float4 x0 = s0v[i4], x1 = s1v[i4], x2 = s2v[i4], x3 = s3v[i4];
                a0 += w.x * x0.x + w.y * x0.y + w.z * x0.z + w.w * x0.w;
                a1 += w.x * x1.x + w.y * x1.y + w.z * x1.z + w.w * x1.w;
                a2 += w.x * x2.x + w.y * x2.y + w.z * x2.z + w.w * x2.w;
                a3 += w.x * x3.x + w.y * x3.y + w.z * x3.z + w.w * x3.w;
            }
        }
        part[0][tid] = a0; part[1][tid] = a1; part[2][tid] = a2; part[3][tid] = a3;
        __syncthreads();

        float y[4];
        if (half == 0) {
            #pragma unroll
            for (int r = 0; r < 4; r++) {
                int e = ebase + r;
                y[r] = part[r][col] + part[r][256 + col] + bias1
                     + g_embW1[wid[e] * H_ + col];
                float v = (col == 0) ? 0.f : y[r] * y[r];
                #pragma unroll
                for (int o = 16; o > 0; o >>= 1) v += __shfl_down_sync(0xffffffffu, v, o);
                if (lane == 0) redsh[r][warp] = v;
                if (col == 0) ybc[r] = y[r];
            }
        }
        __syncthreads();
        if (half == 0) {
            #pragma unroll
            for (int r = 0; r < 4; r++) {
                float ss = 0.f;
                #pragma unroll
                for (int w8 = 0; w8 < 8; w8++) ss += redsh[r][w8];
                float time = e_s1 / (1.f + expf(-ybc[r])) + 1.1f;
                float sc = sqrtf((time * time - 1.f) / fmaxf(ss, 1e-8f));
                float outv = (col == 0) ? time : y[r] * sc;
                g_hbuf[(ebase + r) * H_ + col] = outv;
                shv[r][col] = outv;
            }
        }
        __syncthreads();

        // ---- phase 3: h1 = new_h @ W0T (K=256, halves, packed float4) ----
        float c0 = 0.f, c1 = 0.f, c2 = 0.f, c3 = 0.f;
        {
            const float4* s0v = (const float4*)&shv[0][half * 128];
            const float4* s1v = (const float4*)&shv[1][half * 128];
            const float4* s2v = (const float4*)&shv[2][half * 128];
            const float4* s3v = (const float4*)&shv[3][half * 128];
            #pragma unroll 8
            for (int i4 = 0; i4 < 32; i4++) {
                float4 w = w0p[i4 * 256];
                float4 x0 = s0v[i4], x1 = s1v[i4], x2 = s2v[i4], x3 = s3v[i4];
                c0 += w.x * x0.x + w.y * x0.y + w.z * x0.z + w.w * x0.w;
                c1 += w.x * x1.x + w.y * x1.y + w.z * x1.z + w.w * x1.w;
                c2 += w.x * x2.x + w.y * x2.y + w.z * x2.z + w.w * x2.w;
                c3 += w.x * x3.x + w.y * x3.y + w.z * x3.z + w.w * x3.w;
            }
        }
        part[0][tid] = c0; part[1][tid] = c1; part[2][tid] = c2; part[3][tid] = c3;
        __syncthreads();

        if (half == 0) {
            #pragma unroll
            for (int r = 0; r < 4; r++) {
                y[r] = part[r][col] + part[r][256 + col] + bias0;
                float v = (col == 0) ? 0.f : y[r] * y[r];
                #pragma unroll
                for (int o = 16; o > 0; o >>= 1) v += __shfl_down_sync(0xffffffffu, v, o);
                if (lane == 0) redsh[r][warp] = v;
                if (col == 0) ybc[r] = y[r];
            }
        }
        __syncthreads();
        if (half == 0) {
            #pragma unroll
            for (int r = 0; r < 4; r++) {
                float ss = 0.f;
                #pragma unroll
                for (int w8 = 0; w8 < 8; w8++) ss += redsh[r][w8];
                float time = e_s0 / (1.f + expf(-ybc[r])) + 1.1f;
                float sc = sqrtf((time * time - 1.f) / fmaxf(ss, 1e-8f));
                g_h1buf[(ebase + r) * H_ + col] = (col == 0) ? time : y[r] * sc;
            }
        }

        // ---- grid barrier -------------------------------------------------
        __threadfence();
        __syncthreads();
        if (tid == 0) {
            atomicAdd((int*)&g_bar[t], 1);
            while (g_bar[t] < NB_) __nanosleep(64);
        }
        __syncthreads();
    }
}

// ------------------------- build X rows (256-wide) ------------------------
__global__ void xbuild(const int* __restrict__ bidx, const float* __restrict__ xtv) {
    int row = blockIdx.x, tid = threadIdx.x;  // 256 threads
    float v;
    if (row < E_) {
        if (tid == 0) {
            float n0 = g_hbuf[row * H_];
            float c0 = xtv[bidx[row] * L_];
            v = sqrtf(fmaxf(n0 * n0 + c0 * c0 - 1.f, 1e-8f));
        } else {
            v = g_hbuf[row * H_ + tid];
        }
    } else {
        if (tid == 0) {
            float c0 = xtv[(row - E_) * L_];
            v = sqrtf(fmaxf(c0 * c0, 1e-8f));
        } else {
            v = 0.f;
        }
    }
    g_X[row * H_ + tid] = v;
}

// -------------- fused centroid scores GEMM (K=256) + CE + argmax ----------
__global__ void __launch_bounds__(256) scores_ce_kernel(
    const float* __restrict__ wbias,
    const int*   __restrict__ bidx,
    const int*   __restrict__ dir,
    const int*   __restrict__ ptg,
    const int*   __restrict__ rwid) {
    extern __shared__ float dsm[];
    float* xs  = dsm;                // [16][256]
    float* scr = dsm + 16 * 256;     // [16][788]
    __shared__ int sbid[16];
    int rb = blockIdx.x * 16, tid = threadIdx.x;
    for (int idx = tid; idx < 16 * 256; idx += 256) xs[idx] = g_X[rb * H_ + idx];
    if (tid < 16) {
        int row = rb + tid;
        sbid[tid] = (row < E_) ? bidx[row] : (row - E_);
    }
    __syncthreads();

    const float4* gp = (const float4*)g_GtP;
    for (int cc = 0; cc < 4; cc++) {
        int colv = cc * 256 + tid;
        if (colv < V_) {
            float acc[16];
            #pragma unroll
            for (int r = 0; r < 16; r++) acc[r] = 0.f;
            #pragma unroll 4
            for (int i4 = 0; i4 < 64; i4++) {
                float4 g = gp[i4 * V_ + colv];
                #pragma unroll
                for (int r = 0; r < 16; r++) {
                    float4 xv = *(const float4*)&xs[r * 256 + i4 * 4];
                    acc[r] += g.x * xv.x + g.y * xv.y + g.z * xv.z + g.w * xv.w;
                }
            }
            float bb = wbias[colv];
            #pragma unroll
            for (int r = 0; r < 16; r++) {
                float cg = g_ctxG[sbid[r] * V_ + colv];
                scr[r * 788 + colv] = 2.f + 2.f * (acc[r] + cg) + bb;
            }
        }
    }
    __syncthreads();

    int w = tid >> 5, lane = tid & 31;
    #pragma unroll
    for (int rr = 0; rr < 2; rr++) {
        int r = w * 2 + rr;
        int row = rb + r;
        const float* s = scr + r * 788;
        float mx = -1e30f; int mi = 0x7fffffff;
        for (int j = lane; j < V_; j += 32) {
            float v = s[j];
            if (v > mx) { mx = v; mi = j; }
        }
        #pragma unroll
        for (int o = 16; o > 0; o >>= 1) {
            float om = __shfl_down_sync(0xffffffffu, mx, o);
            int   oi = __shfl_down_sync(0xffffffffu, mi, o);
            if (om > mx || (om == mx && oi < mi)) { mx = om; mi = oi; }
        }
        mx = __shfl_sync(0xffffffffu, mx, 0);
        mi = __shfl_sync(0xffffffffu, mi, 0);
        float p = 0.f;
        for (int j = lane; j < V_; j += 32) p += __expf(s[j] - mx);
        #pragma unroll
        for (int o = 16; o > 0; o >>= 1) p += __shfl_down_sync(0xffffffffu, p, o);
        if (lane == 0) {
            float lse = mx + logf(p);
            if (row < E_) {
                float pm = (float)dir[row];
                int tgt = ptg[row];
                float ce = lse - s[tgt];
                atomicAdd(&g_acc[0], (double)(pm * ce));
                atomicAdd(&g_acc[1], (double)(pm * ((mi == tgt) ? 1.f : 0.f)));
                atomicAdd(&g_acc[2], (double)pm);
            } else {
                int tgt = rwid[row - E_];
                float ce = lse - s[tgt];
                atomicAdd(&g_acc[0], (double)ce);
                atomicAdd(&g_acc[1], (mi == tgt) ? 1.0 : 0.0);
            }
        }
    }
}

// ------------------------- stop head --------------------------------------
__global__ void stop_kernel(const int*   __restrict__ wid,
                            const int*   __restrict__ noi,
                            const float* __restrict__ now,
                            const int*   __restrict__ bidx,
                            const int*   __restrict__ dir,
                            const int*   __restrict__ rwid,
                            const int*   __restrict__ roi,
                            const float* __restrict__ row_w,
                            const float* __restrict__ xtv,
                            const float* __restrict__ emb,
                            const float* __restrict__ ucls,
                            const float* __restrict__ ubias) {
    int row = blockIdx.x, tid = threadIdx.x;
    __shared__ float red[32];
    int widx, tgt;
    const int* oidx; const float* ow; const float* ctx;
    if (row < E_) {
        widx = wid[row]; tgt = dir[row];
        oidx = noi + row * K_; ow = now + row * K_;
        ctx = xtv + bidx[row] * L_;
    } else {
        int b = row - E_;
        widx = rwid[b]; tgt = 0;
        oidx = roi + b * K_; ow = row_w + b * K_;
        ctx = xtv + b * L_;
    }
    float wsum = 0.f, a = 0.f;
    #pragma unroll
    for (int k = 0; k < K_; k++) {
        int id = oidx[k]; float w = ow[k];
        wsum += w;
        a += w * g_hbuf[id * H_ + tid];
    }
    a /= fmaxf(wsum, 1e-8f);
    float inner = blockReduceSum((tid == 0) ? -a * a : a * a, red);
    float co = a / sqrtf(fmaxf(-inner, 1e-8f));
    float cx = emb[widx * H_ + tid];
    float d0, d1;
    if (tid == 0) {
        float t2s = fmaxf(cx * cx + co * co - 1.f, 1e-8f);
        float c0 = ctx[0];
        float x0 = sqrtf(fmaxf(t2s + c0 * c0 - 1.f, 1e-8f));
        d0 = -x0 * ucls[0];
        d1 = -x0 * ucls[DS_];
    } else {
        d0 = cx * ucls[tid] + co * ucls[255 + tid];
        d1 = cx * ucls[DS_ + tid] + co * ucls[DS_ + 255 + tid];
        if (tid < L_) {
            float cv = ctx[tid];
            d0 += cv * ucls[510 + tid];
            d1 += cv * ucls[DS_ + 510 + tid];
        }
    }
    float sc0 = blockReduceSum(d0, red);
    float sc1 = blockReduceSum(d1, red);
    if (tid == 0) {
        sc0 = 2.f + 2.f * sc0 + ubias[0];
        sc1 = 2.f + 2.f * sc1 + ubias[1];
        float mxv = fmaxf(sc0, sc1);
        float lse = mxv + logf(expf(sc0 - mxv) + expf(sc1 - mxv));
        float ce = lse - ((tgt == 0) ? sc0 : sc1);
        int am = (sc1 > sc0) ? 1 : 0;
        atomicAdd(&g_acc[3], (double)ce);
        atomicAdd(&g_acc[4], (am == tgt) ? 1.0 : 0.0);
    }
}

// ------------------------- finalize ---------------------------------------
__global__ void finalize(float* __restrict__ out) {
    out[0] = (float)(g_acc[0] / (double)B_);
    out[1] = (float)(g_acc[3] / (double)B_);
    out[2] = (float)(g_acc[1] / ((double)B_ + g_acc[2]));
    out[3] = (float)(g_acc[4] / (double)(E_ + B_));
}

// ------------------------- launch ------------------------------------------
extern "C" void kernel_launch(void* const* d_in, const int* in_sizes, int n_in,
                              void* d_out, int out_size) {
    const int*   wid   = (const int*)  d_in[0];
    const int*   nhi   = (const int*)  d_in[1];
    const float* nhw   = (const float*)d_in[2];
    const int*   noi   = (const int*)  d_in[3];
    const float* now_  = (const float*)d_in[4];
    const int*   bidx  = (const int*)  d_in[5];
    const int*   dir   = (const int*)  d_in[6];
    const int*   ptg   = (const int*)  d_in[7];
    const int*   rwid  = (const int*)  d_in[8];
    const int*   roi   = (const int*)  d_in[9];
    const float* row_w = (const float*)d_in[10];
    const float* xtv   = (const float*)d_in[11];
    const float* emb   = (const float*)d_in[12];
    const float* W0    = (const float*)d_in[13];
    const float* b0    = (const float*)d_in[14];
    const float* s0    = (const float*)d_in[15];
    const float* W1    = (const float*)d_in[16];
    const float* b1    = (const float*)d_in[17];
    const float* s1    = (const float*)d_in[18];
    const float* wcls  = (const float*)d_in[19];
    const float* wbias = (const float*)d_in[20];
    const float* ucls  = (const float*)d_in[21];
    const float* ubias = (const float*)d_in[22];
    float* out = (float*)d_out;

    const int smem_ce = (16 * 256 + 16 * 788) * sizeof(float);  // ~66 KB
    cudaFuncSetAttribute(scores_ce_kernel,
                         cudaFuncAttributeMaxDynamicSharedMemorySize, smem_ce);

    prep_misc<<<1024, 256>>>(W0, W1, wcls);
    prep_pad<<<1, 256>>>(W0, b0, s0);
    prep_embW1<<<(V_ + 15) / 16, 256>>>(emb);
    prep_ctxG<<<B_, 256>>>(xtv);
    scan_kernel<<<NB_, 512>>>(wid, nhi, nhw, emb, b0, s0, b1, s1);
    xbuild<<<NROWS, 256>>>(bidx, xtv);
    scores_ce_kernel<<<NROWS / 16, 256, smem_ce>>>(wbias, bidx, dir, ptg, rwid);
    stop_kernel<<<NROWS, 256>>>(wid, noi, now_, bidx, dir, rwid, roi, row_w,
                                xtv, emb, ucls, ubias);
    finalize<<<1, 1>>>(out);
}

// round 9
// speedup vs baseline: 2.2334x; 1.2553x over previous
#include <cuda_runtime.h>
#include <math.h>

#define T_ 64
#define M_ 256
#define K_ 6
#define B_ 256
#define H_ 256
#define L_ 128
#define V_ 780
#define E_ 16384
#define DC_ 383          // wcls cols = H+L-1
#define DS_ 638          // ucls cols = 2H+L-2
#define NROWS (E_ + B_)  // msg rows + root rows
#define NB_ 128          // scan blocks (must all be resident; 128 <= 148 SMs)

// ------------------------- device scratch --------------------------------
__device__ __align__(16) float  g_hbuf [(E_ + 1) * H_];
__device__ __align__(16) float  g_h1buf[(E_ + 1) * H_];
__device__ __align__(16) float  g_W1T  [512 * H_];      // for embW1 prep
__device__ __align__(16) float  g_W1P  [H_ * H_];       // packed: [(k>>2)*256+col]*4+(k&3)
__device__ __align__(16) float  g_W0P  [H_ * H_];       // packed W0^T
__device__ __align__(16) float  g_embW1[V_ * H_];       // emb_spatial @ W1^T_spatial
__device__ __align__(16) float  g_GtP  [256 * V_];      // packed rows 0..255
__device__ __align__(16) float  g_GtC  [128 * V_];      // packed ctx rows 256..383 (row 383 = 0)
__device__ __align__(16) float  g_ctxG [B_ * V_];       // ctx_spatial(b) . Gt[256..382]
__device__ __align__(16) float  g_X    [NROWS * H_];    // [x0, h_spatial]
__device__ double g_acc[6];
__device__ volatile int g_bar[T_];

// ------------------------- helpers ---------------------------------------
__device__ __forceinline__ float blockReduceSum(float v, float* sh) {
    __syncthreads();
    #pragma unroll
    for (int o = 16; o > 0; o >>= 1) v += __shfl_down_sync(0xffffffffu, v, o);
    int tid = threadIdx.x;
    if ((tid & 31) == 0) sh[tid >> 5] = v;
    __syncthreads();
    if (tid < 32) {
        int nw = (blockDim.x + 31) >> 5;
        v = (tid < nw) ? sh[tid] : 0.f;
        #pragma unroll
        for (int o = 16; o > 0; o >>= 1) v += __shfl_down_sync(0xffffffffu, v, o);
        if (tid == 0) sh[0] = v;
    }
    __syncthreads();
    return sh[0];
}

__device__ __forceinline__ float gt_val(int i, int v, const float* wcls) {
    if (i == 0)  return -wcls[v * DC_];
    if (i < DC_) return wcls[v * DC_ + i];
    return 0.f;
}

// ------------------------- prep -------------------------------------------
__global__ void prep_misc(const float* __restrict__ W0,
                          const float* __restrict__ W1,
                          const float* __restrict__ wcls) {
    if (blockIdx.x == 0 && threadIdx.x < T_) g_bar[threadIdx.x] = 0;
    const int n1 = 512 * H_;        // W1T
    const int n2 = H_ * H_;         // W1P
    const int n3 = H_ * H_;         // W0P
    const int n4 = 256 * V_;        // GtP
    const int n5 = 128 * V_;        // GtC
    for (int idx = blockIdx.x * blockDim.x + threadIdx.x;
         idx < n1 + n2 + n3 + n4 + n5; idx += gridDim.x * blockDim.x) {
        if (idx < n1) {
            int i = idx >> 8, j = idx & 255;
            g_W1T[idx] = (i < 511) ? W1[j * 511 + i] : 0.f;
        } else if (idx < n1 + n2) {
            int k = idx - n1;
            int i = k >> 8, j = k & 255;   // W1B row i, col j
            float val = (i == 0) ? W1[j * 511] : W1[j * 511 + 255 + i];
            g_W1P[((i >> 2) << 10) + (j << 2) + (i & 3)] = val;
        } else if (idx < n1 + n2 + n3) {
            int k = idx - n1 - n2;
            int i = k >> 8, j = k & 255;   // W0T row i, col j
            g_W0P[((i >> 2) << 10) + (j << 2) + (i & 3)] = W0[j * H_ + i];
        } else if (idx < n1 + n2 + n3 + n4) {
            int k = idx - n1 - n2 - n3;
            int i = k / V_, v = k % V_;    // rows 0..255
            g_GtP[(((i >> 2) * V_ + v) << 2) + (i & 3)] = gt_val(i, v, wcls);
        } else {
            int k = idx - n1 - n2 - n3 - n4;
            int j = k / V_, v = k % V_;    // ctx rows: Gt row 256+j, j=0..127
            g_GtC[(((j >> 2) * V_ + v) << 2) + (j & 3)] = gt_val(256 + j, v, wcls);
        }
    }
}

__global__ void prep_pad(const float* __restrict__ W0,
                         const float* __restrict__ b0,
                         const float* __restrict__ s0p) {
    __shared__ float red[32];
    __shared__ float ybc;
    int tid = threadIdx.x;
    if (tid < 6) g_acc[tid] = 0.0;
    g_hbuf[E_ * H_ + tid] = (tid == 0) ? 1.f : 0.f;
    float y = W0[tid * H_] + b0[tid];
    if (tid == 0) ybc = y;
    float ss = blockReduceSum((tid == 0) ? 0.f : y * y, red);
    float time = expf(s0p[0]) / (1.f + expf(-ybc)) + 1.1f;
    float sc = sqrtf((time * time - 1.f) / fmaxf(ss, 1e-8f));
    g_h1buf[E_ * H_ + tid] = (tid == 0) ? time : y * sc;
}

// embW1[v][j] = sum_{i=1..255} emb[v][i] * W1T[i][j]
__global__ void prep_embW1(const float* __restrict__ emb) {
    __shared__ float es[16][256];
    int v0 = blockIdx.x * 16, tid = threadIdx.x;
    for (int i = tid; i < 16 * 256; i += 256) {
        int r = i >> 8, c = i & 255;
        es[r][c] = (v0 + r < V_) ? emb[(v0 + r) * H_ + c] : 0.f;
    }
    __syncthreads();
    float acc[16];
    #pragma unroll
    for (int r = 0; r < 16; r++) acc[r] = 0.f;
    for (int i = 1; i < 256; i++) {
        float w = g_W1T[i * H_ + tid];
        #pragma unroll
        for (int r = 0; r < 16; r++) acc[r] += es[r][i] * w;
    }
    #pragma unroll
    for (int r = 0; r < 16; r++)
        if (v0 + r < V_) g_embW1[(v0 + r) * H_ + tid] = acc[r];
}

// ctxG[b][v] = sum_{j=0..126} xtv[b][1+j] * Gt[256+j][v]  (packed GtC)
__global__ void prep_ctxG(const float* __restrict__ xtv) {
    __shared__ float4 cs[32];
    int b = blockIdx.x, tid = threadIdx.x;
    if (tid < 128) {
        float v = (tid < 127) ? xtv[b * L_ + 1 + tid] : 0.f;
        ((float*)cs)[tid] = v;
    }
    __syncthreads();
    const float4* gc = (const float4*)g_GtC;
    for (int v = tid; v < V_; v += 256) {
        float acc = 0.f;
        #pragma unroll 8
        for (int j4 = 0; j4 < 32; j4++) {
            float4 g = gc[j4 * V_ + v];
            float4 c = cs[j4];
            acc += g.x * c.x + g.y * c.y + g.z * c.z + g.w * c.w;
        }
        g_ctxG[b * V_ + v] = acc;
    }
}

// ------------------------- persistent scan kernel -------------------------
// 128 blocks x 512 threads, 2 rows/block (row = half). GEMM K split across
// halves with part[] reduce; packed float4 weights.
__global__ void __launch_bounds__(512, 1) scan_kernel(
    const int*   __restrict__ wid,
    const int*   __restrict__ nhi,
    const float* __restrict__ nhw,
    const float* __restrict__ emb,
    const float* __restrict__ b0,
    const float* __restrict__ s0p,
    const float* __restrict__ b1,
    const float* __restrict__ s1p) {
    __shared__ float svec[2][256];
    __shared__ float shv [2][256];
    __shared__ float part[2][512];
    __shared__ float redsh[2][8];
    __shared__ float ybc[2];

    int tid  = threadIdx.x;
    int col  = tid & 255;
    int half = tid >> 8;
    int warp = tid >> 5;
    int lane = tid & 31;
    int bx   = blockIdx.x;
    float e_s0 = expf(s0p[0]);
    float e_s1 = expf(s1p[0]);
    float bias1 = b1[col];
    float bias0 = b0[col];

    const float4* w1p = (const float4*)g_W1P + half * 32 * 256 + col;
    const float4* w0p = (const float4*)g_W0P + half * 32 * 256 + col;

    for (int t = 0; t < T_; t++) {
        int e = t * M_ + bx * 2 + half;   // this half's row

        // ---- phase 1: gathered midpoint on h1buf, build svec[half] -------
        {
            float wsum = 0.f, a = 0.f;
            #pragma unroll
            for (int k = 0; k < K_; k++) {
                int   id = nhi[e * K_ + k];
                float w  = nhw[e * K_ + k];
                wsum += w;
                a += w * g_h1buf[id * H_ + col];
            }
            a /= fmaxf(wsum, 1e-8f);
            float v = (col == 0) ? a * a : -a * a;
            #pragma unroll
            for (int o = 16; o > 0; o >>= 1) v += __shfl_down_sync(0xffffffffu, v, o);
            if (lane == 0) redsh[half][warp & 7] = v;
            __syncthreads();
            float inn = 0.f;
            #pragma unroll
            for (int w8 = 0; w8 < 8; w8++) inn += redsh[half][w8];
            float h1m = a / sqrtf(fmaxf(inn, 1e-8f));
            if (col == 0) {
                float cx0 = emb[wid[e] * H_];
                svec[half][0] = sqrtf(fmaxf(cx0 * cx0 + h1m * h1m - 1.0f, 1e-8f));
            } else {
                svec[half][col] = h1m;
            }
        }
        __syncthreads();

        // ---- phase 2: Y = svec @ W1 (K split across halves) --------------
        float a0 = 0.f, a1 = 0.f;
        {
            const float4* s0v = (const float4*)&svec[0][half * 128];
            const float4* s1v = (const float4*)&svec[1][half * 128];
            #pragma unroll 8
            for (int i4 = 0; i4 < 32; i4++) {
                float4 w = w1p[i4 * 256];
                float4 x0 = s0v[i4], x1 = s1v[i4];
                a0 += w.x * x0.x + w.y * x0.y + w.z * x0.z + w.w * x0.w;
                a1 += w.x * x1.x + w.y * x1.y + w.z * x1.z + w.w * x1.w;
            }
        }
        part[0][tid] = a0; part[1][tid] = a1;
        __syncthreads();

        // epilogue: each half finishes its own row
        {
            float y = part[half][col] + part[half][256 + col] + bias1
                    + g_embW1[wid[e] * H_ + col];
            float v = (col == 0) ? 0.f : y * y;
            #pragma unroll
            for (int o = 16; o > 0; o >>= 1) v += __shfl_down_sync(0xffffffffu, v, o);
            if (lane == 0) redsh[half][warp & 7] = v;
            if (col == 0) ybc[half] = y;
            __syncthreads();
            float ss = 0.f;
            #pragma unroll
            for (int w8 = 0; w8 < 8; w8++) ss += redsh[half][w8];
            float time = e_s1 / (1.f + expf(-ybc[half])) + 1.1f;
            float sc = sqrtf((time * time - 1.f) / fmaxf(ss, 1e-8f));
            float outv = (col == 0) ? time : y * sc;
            g_hbuf[e * H_ + col] = outv;
            shv[half][col] = outv;
        }
        __syncthreads();

        // ---- phase 3: h1 = new_h @ W0T (K split across halves) -----------
        float c0 = 0.f, c1 = 0.f;
        {
            const float4* s0v = (const float4*)&shv[0][half * 128];
            const float4* s1v = (const float4*)&shv[1][half * 128];
            #pragma unroll 8
            for (int i4 = 0; i4 < 32; i4++) {
                float4 w = w0p[i4 * 256];
                float4 x0 = s0v[i4], x1 = s1v[i4];
                c0 += w.x * x0.x + w.y * x0.y + w.z * x0.z + w.w * x0.w;
                c1 += w.x * x1.x + w.y * x1.y + w.z * x1.z + w.w * x1.w;
            }
        }
        part[0][tid] = c0; part[1][tid] = c1;
        __syncthreads();

        {
            float y = part[half][col] + part[half][256 + col] + bias0;
            float v = (col == 0) ? 0.f : y * y;
            #pragma unroll
            for (int o = 16; o > 0; o >>= 1) v += __shfl_down_sync(0xffffffffu, v, o);
            if (lane == 0) redsh[half][warp & 7] = v;
            if (col == 0) ybc[half] = y;
            __syncthreads();
            float ss = 0.f;
            #pragma unroll
            for (int w8 = 0; w8 < 8; w8++) ss += redsh[half][w8];
            float time = e_s0 / (1.f + expf(-ybc[half])) + 1.1f;
            float sc = sqrtf((time * time - 1.f) / fmaxf(ss, 1e-8f));
            g_h1buf[e * H_ + col] = (col == 0) ? time : y * sc;
        }

        // ---- grid barrier -------------------------------------------------
        __threadfence();
        __syncthreads();
        if (tid == 0) {
            atomicAdd((int*)&g_bar[t], 1);
            while (g_bar[t] < NB_) __nanosleep(64);
        }
        __syncthreads();
    }
}

// ------------------------- build X rows (256-wide) ------------------------
__global__ void xbuild(const int* __restrict__ bidx, const float* __restrict__ xtv) {
    int row = blockIdx.x, tid = threadIdx.x;  // 256 threads
    float v;
    if (row < E_) {
        if (tid == 0) {
            float n0 = g_hbuf[row * H_];
            float c0 = xtv[bidx[row] * L_];
            v = sqrtf(fmaxf(n0 * n0 + c0 * c0 - 1.f, 1e-8f));
        } else {
            v = g_hbuf[row * H_ + tid];
        }
    } else {
        if (tid == 0) {
            float c0 = xtv[(row - E_) * L_];
            v = sqrtf(fmaxf(c0 * c0, 1e-8f));
        } else {
            v = 0.f;
        }
    }
    g_X[row * H_ + tid] = v;
}

// -------------- fused centroid scores GEMM (K=256) + CE + argmax ----------
__global__ void __launch_bounds__(256) scores_ce_kernel(
    const float* __restrict__ wbias,
    const int*   __restrict__ bidx,
    const int*   __restrict__ dir,
    const int*   __restrict__ ptg,
    const int*   __restrict__ rwid) {
    extern __shared__ float dsm[];
    float* xs  = dsm;                // [16][256]
    float* scr = dsm + 16 * 256;     // [16][788]
    __shared__ int sbid[16];
    int rb = blockIdx.x * 16, tid = threadIdx.x;
    for (int idx = tid; idx < 16 * 256; idx += 256) xs[idx] = g_X[rb * H_ + idx];
    if (tid < 16) {
        int row = rb + tid;
        sbid[tid] = (row < E_) ? bidx[row] : (row - E_);
    }
    __syncthreads();

    const float4* gp = (const float4*)g_GtP;
    for (int cc = 0; cc < 4; cc++) {
        int colv = cc * 256 + tid;
        if (colv < V_) {
            float acc[16];
            #pragma unroll
            for (int r = 0; r < 16; r++) acc[r] = 0.f;
            #pragma unroll 4
            for (int i4 = 0; i4 < 64; i4++) {
                float4 g = gp[i4 * V_ + colv];
                #pragma unroll
                for (int r = 0; r < 16; r++) {
                    float4 xv = *(const float4*)&xs[r * 256 + i4 * 4];
                    acc[r] += g.x * xv.x + g.y * xv.y + g.z * xv.z + g.w * xv.w;
                }
            }
            float bb = wbias[colv];
            #pragma unroll
            for (int r = 0; r < 16; r++) {
                float cg = g_ctxG[sbid[r] * V_ + colv];
                scr[r * 788 + colv] = 2.f + 2.f * (acc[r] + cg) + bb;
            }
        }
    }
    __syncthreads();

    int w = tid >> 5, lane = tid & 31;
    #pragma unroll
    for (int rr = 0; rr < 2; rr++) {
        int r = w * 2 + rr;
        int row = rb + r;
        const float* s = scr + r * 788;
        float mx = -1e30f; int mi = 0x7fffffff;
        for (int j = lane; j < V_; j += 32) {
            float v = s[j];
            if (v > mx) { mx = v; mi = j; }
        }
        #pragma unroll
        for (int o = 16; o > 0; o >>= 1) {
            float om = __shfl_down_sync(0xffffffffu, mx, o);
            int   oi = __shfl_down_sync(0xffffffffu, mi, o);
            if (om > mx || (om == mx && oi < mi)) { mx = om; mi = oi; }
        }
        mx = __shfl_sync(0xffffffffu, mx, 0);
        mi = __shfl_sync(0xffffffffu, mi, 0);
        float p = 0.f;
        for (int j = lane; j < V_; j += 32) p += __expf(s[j] - mx);
        #pragma unroll
        for (int o = 16; o > 0; o >>= 1) p += __shfl_down_sync(0xffffffffu, p, o);
        if (lane == 0) {
            float lse = mx + logf(p);
            if (row < E_) {
                float pm = (float)dir[row];
                int tgt = ptg[row];
                float ce = lse - s[tgt];
                atomicAdd(&g_acc[0], (double)(pm * ce));
                atomicAdd(&g_acc[1], (double)(pm * ((mi == tgt) ? 1.f : 0.f)));
                atomicAdd(&g_acc[2], (double)pm);
            } else {
                int tgt = rwid[row - E_];
                float ce = lse - s[tgt];
                atomicAdd(&g_acc[0], (double)ce);
                atomicAdd(&g_acc[1], (mi == tgt) ? 1.0 : 0.0);
            }
        }
    }
}

// ------------------------- stop head --------------------------------------
__global__ void stop_kernel(const int*   __restrict__ wid,
                            const int*   __restrict__ noi,
                            const float* __restrict__ now,
                            const int*   __restrict__ bidx,
                            const int*   __restrict__ dir,
                            const int*   __restrict__ rwid,
                            const int*   __restrict__ roi,
                            const float* __restrict__ row_w,
                            const float* __restrict__ xtv,
                            const float* __restrict__ emb,
                            const float* __restrict__ ucls,
                            const float* __restrict__ ubias) {
    int row = blockIdx.x, tid = threadIdx.x;
    __shared__ float red[32];
    int widx, tgt;
    const int* oidx; const float* ow; const float* ctx;
    if (row < E_) {
        widx = wid[row]; tgt = dir[row];
        oidx = noi + row * K_; ow = now + row * K_;
        ctx = xtv + bidx[row] * L_;
    } else {
        int b = row - E_;
        widx = rwid[b]; tgt = 0;
        oidx = roi + b * K_; ow = row_w + b * K_;
        ctx = xtv + b * L_;
    }
    float wsum = 0.f, a = 0.f;
    #pragma unroll
    for (int k = 0; k < K_; k++) {
        int id = oidx[k]; float w = ow[k];
        wsum += w;
        a += w * g_hbuf[id * H_ + tid];
    }
    a /= fmaxf(wsum, 1e-8f);
    float inner = blockReduceSum((tid == 0) ? -a * a : a * a, red);
    float co = a / sqrtf(fmaxf(-inner, 1e-8f));
    float cx = emb[widx * H_ + tid];
    float d0, d1;
    if (tid == 0) {
        float t2s = fmaxf(cx * cx + co * co - 1.f, 1e-8f);
        float c0 = ctx[0];
        float x0 = sqrtf(fmaxf(t2s + c0 * c0 - 1.f, 1e-8f));
        d0 = -x0 * ucls[0];
        d1 = -x0 * ucls[DS_];
    } else {
        d0 = cx * ucls[tid] + co * ucls[255 + tid];
        d1 = cx * ucls[DS_ + tid] + co * ucls[DS_ + 255 + tid];
        if (tid < L_) {
            float cv = ctx[tid];
            d0 += cv * ucls[510 + tid];
            d1 += cv * ucls[DS_ + 510 + tid];
        }
    }
    float sc0 = blockReduceSum(d0, red);
    float sc1 = blockReduceSum(d1, red);
    if (tid == 0) {
        sc0 = 2.f + 2.f * sc0 + ubias[0];
        sc1 = 2.f + 2.f * sc1 + ubias[1];
        float mxv = fmaxf(sc0, sc1);
        float lse = mxv + logf(expf(sc0 - mxv) + expf(sc1 - mxv));
        float ce = lse - ((tgt == 0) ? sc0 : sc1);
        int am = (sc1 > sc0) ? 1 : 0;
        atomicAdd(&g_acc[3], (double)ce);
        atomicAdd(&g_acc[4], (am == tgt) ? 1.0 : 0.0);
    }
}

// ------------------------- finalize ---------------------------------------
__global__ void finalize(float* __restrict__ out) {
    out[0] = (float)(g_acc[0] / (double)B_);
    out[1] = (float)(g_acc[3] / (double)B_);
    out[2] = (float)(g_acc[1] / ((double)B_ + g_acc[2]));
    out[3] = (float)(g_acc[4] / (double)(E_ + B_));
}

// ------------------------- launch ------------------------------------------
extern "C" void kernel_launch(void* const* d_in, const int* in_sizes, int n_in,
                              void* d_out, int out_size) {
    const int*   wid   = (const int*)  d_in[0];
    const int*   nhi   = (const int*)  d_in[1];
    const float* nhw   = (const float*)d_in[2];
    const int*   noi   = (const int*)  d_in[3];
    const float* now_  = (const float*)d_in[4];
    const int*   bidx  = (const int*)  d_in[5];
    const int*   dir   = (const int*)  d_in[6];
    const int*   ptg   = (const int*)  d_in[7];
    const int*   rwid  = (const int*)  d_in[8];
    const int*   roi   = (const int*)  d_in[9];
    const float* row_w = (const float*)d_in[10];
    const float* xtv   = (const float*)d_in[11];
    const float* emb   = (const float*)d_in[12];
    const float* W0    = (const float*)d_in[13];
    const float* b0    = (const float*)d_in[14];
    const float* s0    = (const float*)d_in[15];
    const float* W1    = (const float*)d_in[16];
    const float* b1    = (const float*)d_in[17];
    const float* s1    = (const float*)d_in[18];
    const float* wcls  = (const float*)d_in[19];
    const float* wbias = (const float*)d_in[20];
    const float* ucls  = (const float*)d_in[21];
    const float* ubias = (const float*)d_in[22];
    float* out = (float*)d_out;

    const int smem_ce = (16 * 256 + 16 * 788) * sizeof(float);  // ~66 KB
    cudaFuncSetAttribute(scores_ce_kernel,
                         cudaFuncAttributeMaxDynamicSharedMemorySize, smem_ce);

    prep_misc<<<1024, 256>>>(W0, W1, wcls);
    prep_pad<<<1, 256>>>(W0, b0, s0);
    prep_embW1<<<(V_ + 15) / 16, 256>>>(emb);
    prep_ctxG<<<B_, 256>>>(xtv);
    scan_kernel<<<NB_, 512>>>(wid, nhi, nhw, emb, b0, s0, b1, s1);
    xbuild<<<NROWS, 256>>>(bidx, xtv);
    scores_ce_kernel<<<NROWS / 16, 256, smem_ce>>>(wbias, bidx, dir, ptg, rwid);
    stop_kernel<<<NROWS, 256>>>(wid, noi, now_, bidx, dir, rwid, roi, row_w,
                                xtv, emb, ucls, ubias);
    finalize<<<1, 1>>>(out);
}